// round 16
// baseline (speedup 1.0000x reference)
#include <cuda_runtime.h>
#include <cuda_fp16.h>
#include <math.h>
#include <stdint.h>

#define D_FEAT 128
#define HID 64
#define GRID_W 147          // persistent work CTAs; CTA GRID_W computes c

// Per-node projected features in fp16 (25.6 MB, L2-resident).
__device__ __half g_yh[(size_t)100000 * 128];
// c vector (float) + bias
__device__ float g_c[HID + 1];
// half2-packed c and W2 for the edge kernel
__device__ __half2 g_ch2[HID / 2];
__device__ __half2 g_w2h2[HID / 2];

// ---------------------------------------------------------------------------
// GEMM smem layout (bytes):
//   B fp16 [128][136h]   at 0        (34816)
//   A fp16 [128][136h]   at 34816    (34816)
//   stage0 f32 [128][132] at 69632   (67584)
//   stage1 f32 [128][132] at 137216  (67584)
// ---------------------------------------------------------------------------
#define SROW 272            // fp16 tile row stride in bytes (136 halves)
#define SM_BH 0
#define SM_AH 34816
#define SM_ST0 69632
#define SM_ST1 137216
#define SM_TOTAL 204800

__device__ __forceinline__ uint32_t smem_u32(const void* p) {
    uint32_t a;
    asm("{ .reg .u64 t; cvta.to.shared.u64 t, %1; cvt.u32.u64 %0, t; }"
        : "=r"(a) : "l"(p));
    return a;
}
__device__ __forceinline__ void cp16(uint32_t s, const void* g) {
    asm volatile("cp.async.cg.shared.global [%0], [%1], 16;" :: "r"(s), "l"(g));
}

__device__ __forceinline__ void mma16816(float* c, const uint32_t* a,
                                         const uint32_t* b) {
    asm volatile(
        "mma.sync.aligned.m16n8k16.row.col.f32.f16.f16.f32 "
        "{%0,%1,%2,%3}, {%4,%5,%6,%7}, {%8,%9}, {%0,%1,%2,%3};"
        : "+f"(c[0]), "+f"(c[1]), "+f"(c[2]), "+f"(c[3])
        : "r"(a[0]), "r"(a[1]), "r"(a[2]), "r"(a[3]), "r"(b[0]), "r"(b[1]));
}

// Issue async copy of tile 'row0' into stage at stOff; zero-fill OOB rows.
__device__ __forceinline__ void load_tile_async(const float* __restrict__ embed,
                                                char* smem, uint32_t sbase,
                                                int stOff, int row0, int M,
                                                int tid) {
    int rows = M - row0;
    if (rows > 128) rows = 128;
#pragma unroll
    for (int i = 0; i < 16; ++i) {
        int ch = tid + i * 256;
        int r = ch >> 5;
        int c = ch & 31;
        if (r < rows) {
            cp16(sbase + stOff + r * 528 + c * 16,
                 embed + (size_t)(row0 + r) * 128 + c * 4);
        } else {
            *(float4*)(smem + stOff + r * 528 + c * 16) =
                make_float4(0.f, 0.f, 0.f, 0.f);
        }
    }
}

// ---------------------------------------------------------------------------
// Kernel 1: persistent fp16 node GEMM (m16n8k16), double-buffered cp.async
// stage, + c-vector CTA.  y[M x 128] = embed[M x 128] @ Wc[128 x 128].
// 256 threads = 8 warps (4 M x 2 N), warp tile 32x64, K=128 via 8 k16-steps.
// ---------------------------------------------------------------------------
__global__ __launch_bounds__(256, 1)
void node_gemm_mma(const float* __restrict__ embed,
                   const float* __restrict__ W1,
                   const float* __restrict__ b1,
                   const float* __restrict__ W2,
                   const float* __restrict__ b2,
                   const int* __restrict__ srcp,
                   const int* __restrict__ dstp,
                   int M, int ntiles) {
    extern __shared__ char smem[];
    int tid = threadIdx.x;

    if (blockIdx.x == GRID_W) {
        // ---- c vector CTA
        float* part = (float*)smem;   // [4][64]
        int j = tid & 63;
        int g = tid >> 6;   // 0..3
        int s = srcp[0];
        int d = dstp[0];
        const float* es = embed + (size_t)s * D_FEAT;
        const float* ed = embed + (size_t)d * D_FEAT;
        float acc = 0.f;
#pragma unroll 16
        for (int t = g * 64; t < g * 64 + 64; ++t) {
            float e = (t < 128) ? es[t] : ed[t - 128];
            acc = fmaf(e, W1[(256 + t) * HID + j], acc);  // 256+t == 384+(t-128)
        }
        part[g * 64 + j] = acc;
        __syncthreads();
        if (tid < 64) {
            float cj = b1[j] + part[j] + part[64 + j] + part[128 + j] + part[192 + j];
            g_c[j] = cj;
            part[j] = cj;
            if (j == 0) g_c[HID] = b2[0];
        }
        __syncthreads();
        if (tid < 32) {
            g_ch2[tid]  = __floats2half2_rn(part[2 * tid], part[2 * tid + 1]);
            g_w2h2[tid] = __floats2half2_rn(W2[2 * tid], W2[2 * tid + 1]);
        }
        return;
    }

    uint32_t sbase = smem_u32(smem);
    const int stOff[2] = {SM_ST0, SM_ST1};

    // Prologue: async-load this CTA's first two tiles.
    load_tile_async(embed, smem, sbase, SM_ST0, blockIdx.x * 128, M, tid);
    asm volatile("cp.async.commit_group;");
    if (blockIdx.x + GRID_W < ntiles) {
        load_tile_async(embed, smem, sbase, SM_ST1,
                        (blockIdx.x + GRID_W) * 128, M, tid);
        asm volatile("cp.async.commit_group;");
    }

    // Build B tile once (WcT fp16): B[j][k] = Wc[k][j], half2 pairs along k.
    for (int idx = tid; idx < 8192; idx += 256) {
        int j  = idx & 127;
        int kh = idx >> 7;
        int c  = (j < 64) ? j : j - 64;
        int base = (j < 64) ? 0 : 128;
        float v0 = W1[(base + 2 * kh) * HID + c];
        float v1 = W1[(base + 2 * kh + 1) * HID + c];
        *(__half2*)(smem + SM_BH + j * SROW + 4 * kh) = __floats2half2_rn(v0, v1);
    }

    int w    = tid >> 5;
    int lane = tid & 31;
    int g    = lane >> 2;
    int tg   = lane & 3;
    int mw   = (w & 3) * 32;
    int nw   = (w >> 2) * 64;

    const char* pa0 = smem + SM_AH + (mw + g) * SROW + tg * 4;
    const char* pb0 = smem + SM_BH + (nw + g) * SROW + tg * 4;

    int buf = 0;
    for (int t = blockIdx.x; t < ntiles; t += GRID_W) {
        // Wait for stage[buf]: one newer group may remain in flight.
        if (t + GRID_W < ntiles) {
            asm volatile("cp.async.wait_group 1;");
        } else {
            asm volatile("cp.async.wait_group 0;");
        }
        __syncthreads();   // stage[buf] resident; prior MMA reads of A done

        // Convert stage[buf] f32 -> A fp16 smem
        {
            const char* st = smem + stOff[buf];
            for (int idx = tid; idx < 2048; idx += 256) {
                int r  = idx >> 4;
                int cc = idx & 15;
                const float* sp = (const float*)(st + r * 528 + cc * 32);
                float4 f0 = *(const float4*)sp;
                float4 f1 = *(const float4*)(sp + 4);
                __half2 h[4];
                h[0] = __floats2half2_rn(f0.x, f0.y);
                h[1] = __floats2half2_rn(f0.z, f0.w);
                h[2] = __floats2half2_rn(f1.x, f1.y);
                h[3] = __floats2half2_rn(f1.z, f1.w);
                *(uint4*)(smem + SM_AH + r * SROW + cc * 16) = *(uint4*)h;
            }
        }
        __syncthreads();   // A ready; stage[buf] free

        int tn2 = t + 2 * GRID_W;
        if (tn2 < ntiles) {
            load_tile_async(embed, smem, sbase, stOff[buf], tn2 * 128, M, tid);
            asm volatile("cp.async.commit_group;");
        }

        float acc[2][8][4];
#pragma unroll
        for (int mi = 0; mi < 2; ++mi)
#pragma unroll
            for (int nj = 0; nj < 8; ++nj)
#pragma unroll
                for (int q = 0; q < 4; ++q) acc[mi][nj][q] = 0.f;

#pragma unroll
        for (int ks = 0; ks < 8; ++ks) {
            int kb = ks * 32;
            uint32_t a[2][4];
#pragma unroll
            for (int mi = 0; mi < 2; ++mi) {
                const char* p = pa0 + mi * 16 * SROW + kb;
                a[mi][0] = *(const uint32_t*)p;
                a[mi][1] = *(const uint32_t*)(p + 8 * SROW);
                a[mi][2] = *(const uint32_t*)(p + 16);
                a[mi][3] = *(const uint32_t*)(p + 8 * SROW + 16);
            }
            uint32_t b[8][2];
#pragma unroll
            for (int nj = 0; nj < 8; ++nj) {
                const char* p = pb0 + nj * 8 * SROW + kb;
                b[nj][0] = *(const uint32_t*)p;
                b[nj][1] = *(const uint32_t*)(p + 16);
            }
#pragma unroll
            for (int mi = 0; mi < 2; ++mi)
#pragma unroll
                for (int nj = 0; nj < 8; ++nj)
                    mma16816(acc[mi][nj], a[mi], b[nj]);
        }

        // Epilogue: fp16 half2 stores to g_yh
        int row0 = t * 128;
#pragma unroll
        for (int mi = 0; mi < 2; ++mi) {
            int r0 = row0 + mw + mi * 16 + g;
            int r1 = r0 + 8;
#pragma unroll
            for (int nj = 0; nj < 8; ++nj) {
                int jc = nw + nj * 8 + tg * 2;
                if (r0 < M)
                    *(__half2*)(g_yh + (size_t)r0 * 128 + jc) =
                        __floats2half2_rn(acc[mi][nj][0], acc[mi][nj][1]);
                if (r1 < M)
                    *(__half2*)(g_yh + (size_t)r1 * 128 + jc) =
                        __floats2half2_rn(acc[mi][nj][2], acc[mi][nj][3]);
            }
        }
        buf ^= 1;
    }
}

// ---------------------------------------------------------------------------
// Kernel 2: edge kernel — 8 edges per warp iteration (2 quads), 8 lanes/edge,
// half2 math, full occupancy. Gate: n*exp(s) / (n*exp(s) + 1 - n).
// ---------------------------------------------------------------------------
__global__ __launch_bounds__(256, 8)
void edge_kernel(const float* __restrict__ noise,
                 const int* __restrict__ col,
                 const int* __restrict__ row,
                 float* __restrict__ out,
                 int E) {
    int lane = threadIdx.x & 31;
    int sub  = lane >> 3;
    int l8   = lane & 7;
    int warp  = blockIdx.x * (blockDim.x >> 5) + (threadIdx.x >> 5);
    int nwarp = gridDim.x * (blockDim.x >> 5);

    uint4 cu = *(const uint4*)&g_ch2[l8 * 4];
    uint4 wu = *(const uint4*)&g_w2h2[l8 * 4];
    const __half2* c2 = (const __half2*)&cu;
    const __half2* w2 = (const __half2*)&wu;
    float bias = g_c[HID];
    __half2 z2 = __float2half2_rn(0.f);

    for (int base = 8 * warp; base < E; base += 8 * nwarp) {
        int e0 = base + sub;
        int e1 = base + 4 + sub;
        bool ok0 = e0 < E, ok1 = e1 < E;
        int i0 = ok0 ? e0 : 0, i1 = ok1 ? e1 : 0;

        int ci0 = col[i0], ri0 = row[i0];
        int ci1 = col[i1], ri1 = row[i1];

        uint4 av0 = __ldg((const uint4*)(g_yh + (size_t)ci0 * 128 + l8 * 8));
        uint4 bv0 = __ldg((const uint4*)(g_yh + (size_t)ri0 * 128 + 64 + l8 * 8));
        uint4 av1 = __ldg((const uint4*)(g_yh + (size_t)ci1 * 128 + l8 * 8));
        uint4 bv1 = __ldg((const uint4*)(g_yh + (size_t)ri1 * 128 + 64 + l8 * 8));

        const __half2* ah0 = (const __half2*)&av0;
        const __half2* bh0 = (const __half2*)&bv0;
        const __half2* ah1 = (const __half2*)&av1;
        const __half2* bh1 = (const __half2*)&bv1;

        __half2 p0 = __hmax2(__hadd2(__hadd2(ah0[0], bh0[0]), c2[0]), z2);
        __half2 p1 = __hmax2(__hadd2(__hadd2(ah0[1], bh0[1]), c2[1]), z2);
        __half2 p2 = __hmax2(__hadd2(__hadd2(ah0[2], bh0[2]), c2[2]), z2);
        __half2 p3 = __hmax2(__hadd2(__hadd2(ah0[3], bh0[3]), c2[3]), z2);
        __half2 q0 = __hmax2(__hadd2(__hadd2(ah1[0], bh1[0]), c2[0]), z2);
        __half2 q1 = __hmax2(__hadd2(__hadd2(ah1[1], bh1[1]), c2[1]), z2);
        __half2 q2 = __hmax2(__hadd2(__hadd2(ah1[2], bh1[2]), c2[2]), z2);
        __half2 q3 = __hmax2(__hadd2(__hadd2(ah1[3], bh1[3]), c2[3]), z2);

        __half2 sa0 = __hfma2(p1, w2[1], __hmul2(p0, w2[0]));
        __half2 sb0 = __hfma2(p3, w2[3], __hmul2(p2, w2[2]));
        __half2 sa1 = __hfma2(q1, w2[1], __hmul2(q0, w2[0]));
        __half2 sb1 = __hfma2(q3, w2[3], __hmul2(q2, w2[2]));

        float2 fa0 = __half22float2(sa0), fb0 = __half22float2(sb0);
        float2 fa1 = __half22float2(sa1), fb1 = __half22float2(sb1);
        float s0 = (fa0.x + fa0.y) + (fb0.x + fb0.y);
        float s1 = (fa1.x + fa1.y) + (fb1.x + fb1.y);

        s0 += __shfl_xor_sync(0xffffffffu, s0, 4);
        s0 += __shfl_xor_sync(0xffffffffu, s0, 2);
        s0 += __shfl_xor_sync(0xffffffffu, s0, 1);
        s1 += __shfl_xor_sync(0xffffffffu, s1, 4);
        s1 += __shfl_xor_sync(0xffffffffu, s1, 2);
        s1 += __shfl_xor_sync(0xffffffffu, s1, 1);

        if (l8 == 0) {
            if (ok0) {
                float n = noise[e0];
                float t = n * __expf(s0 + bias);
                out[e0] = __fdividef(t, t + 1.f - n);
            }
            if (ok1) {
                float n = noise[e1];
                float t = n * __expf(s1 + bias);
                out[e1] = __fdividef(t, t + 1.f - n);
            }
        }
    }
}

// ---------------------------------------------------------------------------
extern "C" void kernel_launch(void* const* d_in, const int* in_sizes, int n_in,
                              void* d_out, int out_size) {
    const float* embed = (const float*)d_in[0];
    const float* W1    = (const float*)d_in[1];
    const float* b1    = (const float*)d_in[2];
    const float* W2    = (const float*)d_in[3];
    const float* b2    = (const float*)d_in[4];
    const float* noise = (const float*)d_in[5];
    const int*   col   = (const int*)d_in[6];
    const int*   row   = (const int*)d_in[7];
    const int*   srcp  = (const int*)d_in[8];
    const int*   dstp  = (const int*)d_in[9];

    int M = in_sizes[0] / D_FEAT;
    int E = in_sizes[6];
    int ntiles = (M + 127) / 128;

    cudaFuncSetAttribute(node_gemm_mma,
                         cudaFuncAttributeMaxDynamicSharedMemorySize, SM_TOTAL);

    node_gemm_mma<<<GRID_W + 1, 256, SM_TOTAL>>>(embed, W1, b1, W2, b2,
                                                 srcp, dstp, M, ntiles);
    edge_kernel<<<4096, 256>>>(noise, col, row, (float*)d_out, E);
}

// round 17
// speedup vs baseline: 1.0291x; 1.0291x over previous
#include <cuda_runtime.h>
#include <cuda_fp16.h>
#include <math.h>
#include <stdint.h>

#define D_FEAT 128
#define HID 64
#define GRID_W 147          // persistent work CTAs; CTA GRID_W computes c

// Per-node projected features in fp16 (25.6 MB, L2-resident).
__device__ __half g_yh[(size_t)100000 * 128];
// c vector (float) + bias
__device__ float g_c[HID + 1];
// half2-packed c and W2 for the edge kernel
__device__ __half2 g_ch2[HID / 2];
__device__ __half2 g_w2h2[HID / 2];

// ---------------------------------------------------------------------------
// GEMM smem layout (bytes):
//   B fp16  [128][136h]   at 0        (34816)
//   stage0 f32 [128][132] at 34816    (67584)
//   stage1 f32 [128][132] at 102400   (67584)
// A fragments are built directly from the f32 stage (LDS.64 + cvt f32x2->h2).
// ---------------------------------------------------------------------------
#define SROW 272            // fp16 B row stride in bytes (136 halves)
#define SROW32 132          // stage row stride in floats (528 B)
#define SM_BH 0
#define SM_ST0 34816
#define SM_ST1 102400
#define SM_TOTAL 169984

__device__ __forceinline__ uint32_t smem_u32(const void* p) {
    uint32_t a;
    asm("{ .reg .u64 t; cvta.to.shared.u64 t, %1; cvt.u32.u64 %0, t; }"
        : "=r"(a) : "l"(p));
    return a;
}
__device__ __forceinline__ void cp16(uint32_t s, const void* g) {
    asm volatile("cp.async.cg.shared.global [%0], [%1], 16;" :: "r"(s), "l"(g));
}

__device__ __forceinline__ void mma16816(float* c, const uint32_t* a,
                                         const uint32_t* b) {
    asm volatile(
        "mma.sync.aligned.m16n8k16.row.col.f32.f16.f16.f32 "
        "{%0,%1,%2,%3}, {%4,%5,%6,%7}, {%8,%9}, {%0,%1,%2,%3};"
        : "+f"(c[0]), "+f"(c[1]), "+f"(c[2]), "+f"(c[3])
        : "r"(a[0]), "r"(a[1]), "r"(a[2]), "r"(a[3]), "r"(b[0]), "r"(b[1]));
}

__device__ __forceinline__ uint32_t f2toh2(float2 f) {
    __half2 h = __floats2half2_rn(f.x, f.y);   // cvt.rn.f16x2.f32
    return *(uint32_t*)&h;
}

// Issue async copy of tile 'row0' into stage at stOff; zero-fill OOB rows.
__device__ __forceinline__ void load_tile_async(const float* __restrict__ embed,
                                                char* smem, uint32_t sbase,
                                                int stOff, int row0, int M,
                                                int tid) {
    int rows = M - row0;
    if (rows > 128) rows = 128;
#pragma unroll
    for (int i = 0; i < 16; ++i) {
        int ch = tid + i * 256;
        int r = ch >> 5;
        int c = ch & 31;
        if (r < rows) {
            cp16(sbase + stOff + r * 528 + c * 16,
                 embed + (size_t)(row0 + r) * 128 + c * 4);
        } else {
            *(float4*)(smem + stOff + r * 528 + c * 16) =
                make_float4(0.f, 0.f, 0.f, 0.f);
        }
    }
}

// ---------------------------------------------------------------------------
// Kernel 1: persistent fp16 node GEMM (m16n8k16), double f32 stage, A frags
// converted inline from the stage. + c-vector CTA.
// 256 threads = 8 warps (4 M x 2 N), warp tile 32x64, K=128 via 8 k16-steps.
// ---------------------------------------------------------------------------
__global__ __launch_bounds__(256, 1)
void node_gemm_mma(const float* __restrict__ embed,
                   const float* __restrict__ W1,
                   const float* __restrict__ b1,
                   const float* __restrict__ W2,
                   const float* __restrict__ b2,
                   const int* __restrict__ srcp,
                   const int* __restrict__ dstp,
                   int M, int ntiles) {
    extern __shared__ char smem[];
    int tid = threadIdx.x;

    if (blockIdx.x == GRID_W) {
        // ---- c vector CTA
        float* part = (float*)smem;   // [4][64]
        int j = tid & 63;
        int g = tid >> 6;   // 0..3
        int s = srcp[0];
        int d = dstp[0];
        const float* es = embed + (size_t)s * D_FEAT;
        const float* ed = embed + (size_t)d * D_FEAT;
        float acc = 0.f;
#pragma unroll 16
        for (int t = g * 64; t < g * 64 + 64; ++t) {
            float e = (t < 128) ? es[t] : ed[t - 128];
            acc = fmaf(e, W1[(256 + t) * HID + j], acc);  // 256+t == 384+(t-128)
        }
        part[g * 64 + j] = acc;
        __syncthreads();
        if (tid < 64) {
            float cj = b1[j] + part[j] + part[64 + j] + part[128 + j] + part[192 + j];
            g_c[j] = cj;
            part[j] = cj;
            if (j == 0) g_c[HID] = b2[0];
        }
        __syncthreads();
        if (tid < 32) {
            g_ch2[tid]  = __floats2half2_rn(part[2 * tid], part[2 * tid + 1]);
            g_w2h2[tid] = __floats2half2_rn(W2[2 * tid], W2[2 * tid + 1]);
        }
        return;
    }

    uint32_t sbase = smem_u32(smem);
    const int stOff[2] = {SM_ST0, SM_ST1};

    // Prologue: async-load this CTA's first two tiles.
    load_tile_async(embed, smem, sbase, SM_ST0, blockIdx.x * 128, M, tid);
    asm volatile("cp.async.commit_group;");
    if (blockIdx.x + GRID_W < ntiles) {
        load_tile_async(embed, smem, sbase, SM_ST1,
                        (blockIdx.x + GRID_W) * 128, M, tid);
        asm volatile("cp.async.commit_group;");
    }

    // Build B tile once (WcT fp16): B[j][k] = Wc[k][j], half2 pairs along k.
    for (int idx = tid; idx < 8192; idx += 256) {
        int j  = idx & 127;
        int kh = idx >> 7;
        int c  = (j < 64) ? j : j - 64;
        int base = (j < 64) ? 0 : 128;
        float v0 = W1[(base + 2 * kh) * HID + c];
        float v1 = W1[(base + 2 * kh + 1) * HID + c];
        *(__half2*)(smem + SM_BH + j * SROW + 4 * kh) = __floats2half2_rn(v0, v1);
    }

    int w    = tid >> 5;
    int lane = tid & 31;
    int g    = lane >> 2;
    int tg   = lane & 3;
    int mw   = (w & 3) * 32;
    int nw   = (w >> 2) * 64;

    const char* pb0 = smem + SM_BH + (nw + g) * SROW + tg * 4;

    int buf = 0;
    for (int t = blockIdx.x; t < ntiles; t += GRID_W) {
        // Wait for stage[buf]: one newer group may remain in flight.
        if (t + GRID_W < ntiles) {
            asm volatile("cp.async.wait_group 1;");
        } else {
            asm volatile("cp.async.wait_group 0;");
        }
        __syncthreads();   // stage[buf] resident

        // A fragment base for this warp in the f32 stage:
        // row (mw+g), float col 2tg.
        const float* pa = (const float*)(smem + stOff[buf])
                          + (mw + g) * SROW32 + 2 * tg;

        float acc[2][8][4];
#pragma unroll
        for (int mi = 0; mi < 2; ++mi)
#pragma unroll
            for (int nj = 0; nj < 8; ++nj)
#pragma unroll
                for (int q = 0; q < 4; ++q) acc[mi][nj][q] = 0.f;

#pragma unroll
        for (int ks = 0; ks < 8; ++ks) {
            int kf = ks * 16;   // float offset of this k16 block
            uint32_t a[2][4];
#pragma unroll
            for (int mi = 0; mi < 2; ++mi) {
                const float* p = pa + mi * 16 * SROW32 + kf;
                a[mi][0] = f2toh2(*(const float2*)p);
                a[mi][1] = f2toh2(*(const float2*)(p + 8 * SROW32));
                a[mi][2] = f2toh2(*(const float2*)(p + 8));
                a[mi][3] = f2toh2(*(const float2*)(p + 8 * SROW32 + 8));
            }
            int kb = ks * 32;   // byte offset in fp16 B tile
            uint32_t b[8][2];
#pragma unroll
            for (int nj = 0; nj < 8; ++nj) {
                const char* p = pb0 + nj * 8 * SROW + kb;
                b[nj][0] = *(const uint32_t*)p;
                b[nj][1] = *(const uint32_t*)(p + 16);
            }
#pragma unroll
            for (int mi = 0; mi < 2; ++mi)
#pragma unroll
                for (int nj = 0; nj < 8; ++nj)
                    mma16816(acc[mi][nj], a[mi], b[nj]);
        }

        __syncthreads();   // all warps done reading stage[buf]

        int tn2 = t + 2 * GRID_W;
        if (tn2 < ntiles) {
            load_tile_async(embed, smem, sbase, stOff[buf], tn2 * 128, M, tid);
            asm volatile("cp.async.commit_group;");
        }

        // Epilogue: fp16 half2 stores to g_yh (overlaps the load above)
        int row0 = t * 128;
#pragma unroll
        for (int mi = 0; mi < 2; ++mi) {
            int r0 = row0 + mw + mi * 16 + g;
            int r1 = r0 + 8;
#pragma unroll
            for (int nj = 0; nj < 8; ++nj) {
                int jc = nw + nj * 8 + tg * 2;
                if (r0 < M)
                    *(__half2*)(g_yh + (size_t)r0 * 128 + jc) =
                        __floats2half2_rn(acc[mi][nj][0], acc[mi][nj][1]);
                if (r1 < M)
                    *(__half2*)(g_yh + (size_t)r1 * 128 + jc) =
                        __floats2half2_rn(acc[mi][nj][2], acc[mi][nj][3]);
            }
        }
        buf ^= 1;
    }
}

// ---------------------------------------------------------------------------
// Kernel 2: edge kernel — 8 edges per warp iteration (2 quads), 8 lanes/edge,
// half2 math, full occupancy. Gate: n*exp(s) / (n*exp(s) + 1 - n).
// ---------------------------------------------------------------------------
__global__ __launch_bounds__(256, 8)
void edge_kernel(const float* __restrict__ noise,
                 const int* __restrict__ col,
                 const int* __restrict__ row,
                 float* __restrict__ out,
                 int E) {
    int lane = threadIdx.x & 31;
    int sub  = lane >> 3;
    int l8   = lane & 7;
    int warp  = blockIdx.x * (blockDim.x >> 5) + (threadIdx.x >> 5);
    int nwarp = gridDim.x * (blockDim.x >> 5);

    uint4 cu = *(const uint4*)&g_ch2[l8 * 4];
    uint4 wu = *(const uint4*)&g_w2h2[l8 * 4];
    const __half2* c2 = (const __half2*)&cu;
    const __half2* w2 = (const __half2*)&wu;
    float bias = g_c[HID];
    __half2 z2 = __float2half2_rn(0.f);

    for (int base = 8 * warp; base < E; base += 8 * nwarp) {
        int e0 = base + sub;
        int e1 = base + 4 + sub;
        bool ok0 = e0 < E, ok1 = e1 < E;
        int i0 = ok0 ? e0 : 0, i1 = ok1 ? e1 : 0;

        int ci0 = col[i0], ri0 = row[i0];
        int ci1 = col[i1], ri1 = row[i1];

        uint4 av0 = __ldg((const uint4*)(g_yh + (size_t)ci0 * 128 + l8 * 8));
        uint4 bv0 = __ldg((const uint4*)(g_yh + (size_t)ri0 * 128 + 64 + l8 * 8));
        uint4 av1 = __ldg((const uint4*)(g_yh + (size_t)ci1 * 128 + l8 * 8));
        uint4 bv1 = __ldg((const uint4*)(g_yh + (size_t)ri1 * 128 + 64 + l8 * 8));

        const __half2* ah0 = (const __half2*)&av0;
        const __half2* bh0 = (const __half2*)&bv0;
        const __half2* ah1 = (const __half2*)&av1;
        const __half2* bh1 = (const __half2*)&bv1;

        __half2 p0 = __hmax2(__hadd2(__hadd2(ah0[0], bh0[0]), c2[0]), z2);
        __half2 p1 = __hmax2(__hadd2(__hadd2(ah0[1], bh0[1]), c2[1]), z2);
        __half2 p2 = __hmax2(__hadd2(__hadd2(ah0[2], bh0[2]), c2[2]), z2);
        __half2 p3 = __hmax2(__hadd2(__hadd2(ah0[3], bh0[3]), c2[3]), z2);
        __half2 q0 = __hmax2(__hadd2(__hadd2(ah1[0], bh1[0]), c2[0]), z2);
        __half2 q1 = __hmax2(__hadd2(__hadd2(ah1[1], bh1[1]), c2[1]), z2);
        __half2 q2 = __hmax2(__hadd2(__hadd2(ah1[2], bh1[2]), c2[2]), z2);
        __half2 q3 = __hmax2(__hadd2(__hadd2(ah1[3], bh1[3]), c2[3]), z2);

        __half2 sa0 = __hfma2(p1, w2[1], __hmul2(p0, w2[0]));
        __half2 sb0 = __hfma2(p3, w2[3], __hmul2(p2, w2[2]));
        __half2 sa1 = __hfma2(q1, w2[1], __hmul2(q0, w2[0]));
        __half2 sb1 = __hfma2(q3, w2[3], __hmul2(q2, w2[2]));

        float2 fa0 = __half22float2(sa0), fb0 = __half22float2(sb0);
        float2 fa1 = __half22float2(sa1), fb1 = __half22float2(sb1);
        float s0 = (fa0.x + fa0.y) + (fb0.x + fb0.y);
        float s1 = (fa1.x + fa1.y) + (fb1.x + fb1.y);

        s0 += __shfl_xor_sync(0xffffffffu, s0, 4);
        s0 += __shfl_xor_sync(0xffffffffu, s0, 2);
        s0 += __shfl_xor_sync(0xffffffffu, s0, 1);
        s1 += __shfl_xor_sync(0xffffffffu, s1, 4);
        s1 += __shfl_xor_sync(0xffffffffu, s1, 2);
        s1 += __shfl_xor_sync(0xffffffffu, s1, 1);

        if (l8 == 0) {
            if (ok0) {
                float n = noise[e0];
                float t = n * __expf(s0 + bias);
                out[e0] = __fdividef(t, t + 1.f - n);
            }
            if (ok1) {
                float n = noise[e1];
                float t = n * __expf(s1 + bias);
                out[e1] = __fdividef(t, t + 1.f - n);
            }
        }
    }
}

// ---------------------------------------------------------------------------
extern "C" void kernel_launch(void* const* d_in, const int* in_sizes, int n_in,
                              void* d_out, int out_size) {
    const float* embed = (const float*)d_in[0];
    const float* W1    = (const float*)d_in[1];
    const float* b1    = (const float*)d_in[2];
    const float* W2    = (const float*)d_in[3];
    const float* b2    = (const float*)d_in[4];
    const float* noise = (const float*)d_in[5];
    const int*   col   = (const int*)d_in[6];
    const int*   row   = (const int*)d_in[7];
    const int*   srcp  = (const int*)d_in[8];
    const int*   dstp  = (const int*)d_in[9];

    int M = in_sizes[0] / D_FEAT;
    int E = in_sizes[6];
    int ntiles = (M + 127) / 128;

    cudaFuncSetAttribute(node_gemm_mma,
                         cudaFuncAttributeMaxDynamicSharedMemorySize, SM_TOTAL);

    node_gemm_mma<<<GRID_W + 1, 256, SM_TOTAL>>>(embed, W1, b1, W2, b2,
                                                 srcp, dstp, M, ntiles);
    edge_kernel<<<4096, 256>>>(noise, col, row, (float*)d_out, E);
}